// round 2
// baseline (speedup 1.0000x reference)
#include <cuda_runtime.h>
#include <cuda_bf16.h>
#include <math.h>

// ---------------- problem constants ----------------
#define N_TOK   4096
#define EMBED   1024
#define NHEADS  16
#define HDIM    64
#define FFN     4096
#define QKV_N   3072

// ---------------- scratch (device globals; no allocation allowed) ----------------
__device__ float g_qkv [N_TOK * QKV_N];   // 50 MB
__device__ float g_attn[N_TOK * EMBED];   // 16 MB
__device__ float g_tmp [N_TOK * EMBED];   // 16 MB
__device__ float g_h   [N_TOK * EMBED];   // 16 MB
__device__ float g_ffn [N_TOK * FFN];     // 64 MB
__device__ int   g_seg [N_TOK];

// ---------------- segment ids: searchsorted(cu[1:], n, 'right') ----------------
__global__ void seg_kernel(const int* __restrict__ cu, int* __restrict__ seg) {
    int n = blockIdx.x * blockDim.x + threadIdx.x;
    if (n < N_TOK) {
        int s = 0;
        #pragma unroll
        for (int j = 1; j <= 8; j++) s += (cu[j] <= n) ? 1 : 0;
        seg[n] = s;
    }
}

// ---------------- fp32 tiled GEMM: C[M,N] = A[M,K] @ B[K,N] + bias (opt GELU) ----------------
#define BM 128
#define BN 128
#define BK 16

__device__ __forceinline__ float gelu_tanh(float x) {
    // jax.nn.gelu approximate=True
    float x3 = x * x * x;
    return 0.5f * x * (1.0f + tanhf(0.7978845608028654f * (x + 0.044715f * x3)));
}

__global__ __launch_bounds__(256) void sgemm_kernel(
    const float* __restrict__ A, const float* __restrict__ B,
    const float* __restrict__ bias, float* __restrict__ C,
    int M, int N, int K, int act)
{
    __shared__ float As[BK][BM];
    __shared__ float Bs[BK][BN];

    const int tid = threadIdx.x;
    const int bm = blockIdx.y * BM;
    const int bn = blockIdx.x * BN;
    const int tx = tid & 15;       // 0..15 (cols)
    const int ty = tid >> 4;       // 0..15 (rows)

    const int arow = tid >> 2;            // 0..63
    const int acol = (tid & 3) << 2;      // 0,4,8,12
    const int brow = tid >> 5;            // 0..7
    const int bcol = (tid & 31) << 2;     // 0..124

    float acc[8][8];
    #pragma unroll
    for (int i = 0; i < 8; i++)
        #pragma unroll
        for (int j = 0; j < 8; j++) acc[i][j] = 0.f;

    const float* Aptr = A + (size_t)bm * K;
    const float* Bptr = B + bn;

    for (int k0 = 0; k0 < K; k0 += BK) {
        #pragma unroll
        for (int r = 0; r < 2; r++) {
            int row = arow + r * 64;
            float4 a = *(const float4*)(Aptr + (size_t)row * K + k0 + acol);
            As[acol + 0][row] = a.x;
            As[acol + 1][row] = a.y;
            As[acol + 2][row] = a.z;
            As[acol + 3][row] = a.w;
        }
        #pragma unroll
        for (int r = 0; r < 2; r++) {
            int row = brow + r * 8;
            *(float4*)(&Bs[row][bcol]) = *(const float4*)(Bptr + (size_t)(k0 + row) * N + bcol);
        }
        __syncthreads();

        #pragma unroll
        for (int kk = 0; kk < BK; kk++) {
            float ar[8], br[8];
            *(float4*)(ar)     = *(const float4*)(&As[kk][ty * 8]);
            *(float4*)(ar + 4) = *(const float4*)(&As[kk][ty * 8 + 4]);
            *(float4*)(br)     = *(const float4*)(&Bs[kk][tx * 8]);
            *(float4*)(br + 4) = *(const float4*)(&Bs[kk][tx * 8 + 4]);
            #pragma unroll
            for (int i = 0; i < 8; i++)
                #pragma unroll
                for (int j = 0; j < 8; j++)
                    acc[i][j] = fmaf(ar[i], br[j], acc[i][j]);
        }
        __syncthreads();
    }

    #pragma unroll
    for (int i = 0; i < 8; i++) {
        int row = bm + ty * 8 + i;
        #pragma unroll
        for (int j = 0; j < 8; j += 4) {
            int col = bn + tx * 8 + j;
            float4 c;
            c.x = acc[i][j + 0] + bias[col + 0];
            c.y = acc[i][j + 1] + bias[col + 1];
            c.z = acc[i][j + 2] + bias[col + 2];
            c.w = acc[i][j + 3] + bias[col + 3];
            if (act) {
                c.x = gelu_tanh(c.x); c.y = gelu_tanh(c.y);
                c.z = gelu_tanh(c.z); c.w = gelu_tanh(c.w);
            }
            *(float4*)(C + (size_t)row * N + col) = c;
        }
    }
}

// ---------------- RoPE (in-place on q and k slices of qkv) ----------------
__global__ __launch_bounds__(128) void rope_kernel(
    float* __restrict__ qkv, const float* __restrict__ coords,
    const float* __restrict__ inv_freq)
{
    int n = blockIdx.x;
    int t = threadIdx.x;
    __shared__ float cs[32], sn[32];
    if (t < 32) {
        // ang[n, d*8+f] = coords[n,d] * inv_freq_flat[d*8+f]
        float ang = coords[n * 4 + (t >> 3)] * inv_freq[t];
        cs[t] = cosf(ang);
        sn[t] = sinf(ang);
    }
    __syncthreads();
    // items: (h,s,i): 16 heads x 2 (q,k) x 32 pairs = 1024
    for (int item = t; item < 1024; item += 128) {
        int i  = item & 31;
        int hs = item >> 5;       // 0..31
        int s  = hs & 1;
        int h  = hs >> 1;
        float* base = qkv + (size_t)n * QKV_N + s * EMBED + h * HDIM;
        float x1 = base[i], x2 = base[i + 32];
        float c = cs[i], si = sn[i];
        base[i]      = x1 * c - x2 * si;
        base[i + 32] = x2 * c + x1 * si;
    }
}

// ---------------- varlen flash attention (fp32, online softmax) ----------------
__global__ __launch_bounds__(32) void attn_kernel(
    const float* __restrict__ qkv, const int* __restrict__ cu,
    const int* __restrict__ seg, float* __restrict__ out)
{
    const int lane = threadIdx.x;
    const int n = blockIdx.x * 32 + lane;
    const int h = blockIdx.y;

    float q[64];
    {
        const float4* qp = (const float4*)(qkv + (size_t)n * QKV_N + h * HDIM);
        #pragma unroll
        for (int i = 0; i < 16; i++) {
            float4 t = qp[i];
            q[4*i] = t.x; q[4*i+1] = t.y; q[4*i+2] = t.z; q[4*i+3] = t.w;
        }
    }

    const int s = seg[n];
    const int start = cu[s];
    const int end   = cu[s + 1];
    int jmin = start, jmax = end;
    #pragma unroll
    for (int off = 16; off; off >>= 1) {
        jmin = min(jmin, __shfl_xor_sync(0xffffffffu, jmin, off));
        jmax = max(jmax, __shfl_xor_sync(0xffffffffu, jmax, off));
    }

    float m = -1e30f, l = 0.f;
    float o[64];
    #pragma unroll
    for (int i = 0; i < 64; i++) o[i] = 0.f;

    for (int j = jmin; j < jmax; j++) {
        const float4* kp = (const float4*)(qkv + (size_t)j * QKV_N + EMBED + h * HDIM);
        float dot = 0.f;
        #pragma unroll
        for (int i = 0; i < 16; i++) {
            float4 t = kp[i];
            dot = fmaf(q[4*i],   t.x, dot);
            dot = fmaf(q[4*i+1], t.y, dot);
            dot = fmaf(q[4*i+2], t.z, dot);
            dot = fmaf(q[4*i+3], t.w, dot);
        }
        dot *= 0.125f;   // 1/sqrt(64)
        if (j >= start && j < end) {
            if (dot > m) {
                float sc = __expf(m - dot);
                l *= sc;
                #pragma unroll
                for (int i = 0; i < 64; i++) o[i] *= sc;
                m = dot;
            }
            float p = __expf(dot - m);
            l += p;
            const float4* vp = (const float4*)(qkv + (size_t)j * QKV_N + 2 * EMBED + h * HDIM);
            #pragma unroll
            for (int i = 0; i < 16; i++) {
                float4 t = vp[i];
                o[4*i]   = fmaf(p, t.x, o[4*i]);
                o[4*i+1] = fmaf(p, t.y, o[4*i+1]);
                o[4*i+2] = fmaf(p, t.z, o[4*i+2]);
                o[4*i+3] = fmaf(p, t.w, o[4*i+3]);
            }
        }
    }

    float inv = 1.f / l;
    float* op = out + (size_t)n * EMBED + h * HDIM;
    #pragma unroll
    for (int i = 0; i < 64; i += 4) {
        float4 t = make_float4(o[i] * inv, o[i+1] * inv, o[i+2] * inv, o[i+3] * inv);
        *(float4*)(op + i) = t;
    }
}

// ---------------- fused residual-add + LayerNorm ----------------
__global__ __launch_bounds__(256) void add_ln_kernel(
    const float* __restrict__ a, const float* __restrict__ b,
    const float* __restrict__ g, const float* __restrict__ beta,
    float* __restrict__ out)
{
    const int n = blockIdx.x;
    const int t = threadIdx.x;
    __shared__ float red[8];
    __shared__ float bc;

    float x[4];
    float s = 0.f;
    #pragma unroll
    for (int i = 0; i < 4; i++) {
        int idx = t + i * 256;
        x[i] = a[(size_t)n * EMBED + idx] + b[(size_t)n * EMBED + idx];
        s += x[i];
    }
    // block sum
    #pragma unroll
    for (int off = 16; off; off >>= 1) s += __shfl_xor_sync(0xffffffffu, s, off);
    if ((t & 31) == 0) red[t >> 5] = s;
    __syncthreads();
    if (t < 8) {
        float v = red[t];
        #pragma unroll
        for (int off = 4; off; off >>= 1) v += __shfl_xor_sync(0xffu, v, off);
        if (t == 0) bc = v;
    }
    __syncthreads();
    float mean = bc * (1.0f / EMBED);
    __syncthreads();

    float var = 0.f;
    #pragma unroll
    for (int i = 0; i < 4; i++) {
        float d = x[i] - mean;
        var += d * d;
    }
    #pragma unroll
    for (int off = 16; off; off >>= 1) var += __shfl_xor_sync(0xffffffffu, var, off);
    if ((t & 31) == 0) red[t >> 5] = var;
    __syncthreads();
    if (t < 8) {
        float v = red[t];
        #pragma unroll
        for (int off = 4; off; off >>= 1) v += __shfl_xor_sync(0xffu, v, off);
        if (t == 0) bc = v;
    }
    __syncthreads();
    float rstd = rsqrtf(bc * (1.0f / EMBED) + 1e-5f);

    #pragma unroll
    for (int i = 0; i < 4; i++) {
        int idx = t + i * 256;
        out[(size_t)n * EMBED + idx] = (x[i] - mean) * rstd * g[idx] + beta[idx];
    }
}

// ---------------- launch ----------------
extern "C" void kernel_launch(void* const* d_in, const int* in_sizes, int n_in,
                              void* d_out, int out_size)
{
    const float* coords  = (const float*)d_in[0];
    const float* feats   = (const float*)d_in[1];
    const int*   cu      = (const int*)  d_in[2];
    const float* Wqkv    = (const float*)d_in[3];
    const float* bqkv    = (const float*)d_in[4];
    const float* Wo      = (const float*)d_in[5];
    const float* bo      = (const float*)d_in[6];
    const float* inv_frq = (const float*)d_in[7];
    const float* ln1_g   = (const float*)d_in[8];
    const float* ln1_b   = (const float*)d_in[9];
    const float* W1      = (const float*)d_in[10];
    const float* b1      = (const float*)d_in[11];
    const float* W2      = (const float*)d_in[12];
    const float* b2      = (const float*)d_in[13];
    const float* ln2_g   = (const float*)d_in[14];
    const float* ln2_b   = (const float*)d_in[15];
    float* out = (float*)d_out;

    float *qkv, *attn, *tmp, *h, *ffn;
    int* seg;
    cudaGetSymbolAddress((void**)&qkv,  g_qkv);
    cudaGetSymbolAddress((void**)&attn, g_attn);
    cudaGetSymbolAddress((void**)&tmp,  g_tmp);
    cudaGetSymbolAddress((void**)&h,    g_h);
    cudaGetSymbolAddress((void**)&ffn,  g_ffn);
    cudaGetSymbolAddress((void**)&seg,  g_seg);

    // 1. segment ids
    seg_kernel<<<16, 256>>>(cu, seg);
    // 2. QKV projection
    sgemm_kernel<<<dim3(QKV_N / BN, N_TOK / BM), 256>>>(feats, Wqkv, bqkv, qkv,
                                                        N_TOK, QKV_N, EMBED, 0);
    // 3. RoPE on q,k
    rope_kernel<<<N_TOK, 128>>>(qkv, coords, inv_frq);
    // 4. varlen attention
    attn_kernel<<<dim3(N_TOK / 32, NHEADS), 32>>>(qkv, cu, seg, attn);
    // 5. output projection
    sgemm_kernel<<<dim3(EMBED / BN, N_TOK / BM), 256>>>(attn, Wo, bo, tmp,
                                                        N_TOK, EMBED, EMBED, 0);
    // 6. h = LN1(feats + o)
    add_ln_kernel<<<N_TOK, 256>>>(feats, tmp, ln1_g, ln1_b, h);
    // 7. FFN up + GELU
    sgemm_kernel<<<dim3(FFN / BN, N_TOK / BM), 256>>>(h, W1, b1, ffn,
                                                      N_TOK, FFN, EMBED, 1);
    // 8. FFN down
    sgemm_kernel<<<dim3(EMBED / BN, N_TOK / BM), 256>>>(ffn, W2, b2, tmp,
                                                        N_TOK, EMBED, FFN, 0);
    // 9. out = LN2(h + f)
    add_ln_kernel<<<N_TOK, 256>>>(h, tmp, ln2_g, ln2_b, out);
}

// round 3
// speedup vs baseline: 1.4061x; 1.4061x over previous
#include <cuda_runtime.h>
#include <cuda_bf16.h>
#include <math.h>

// ---------------- problem constants ----------------
#define N_TOK   4096
#define EMBED   1024
#define NHEADS  16
#define HDIM    64
#define FFN     4096
#define QKV_N   3072

// ---------------- scratch (device globals; no allocation allowed) ----------------
__device__ float g_qkv [N_TOK * QKV_N];
__device__ float g_attn[N_TOK * EMBED];
__device__ float g_tmp [N_TOK * EMBED];
__device__ float g_h   [N_TOK * EMBED];
__device__ float g_ffn [N_TOK * FFN];
__device__ int   g_seg [N_TOK];

// ---------------- helpers ----------------
__device__ __forceinline__ unsigned f2tf(float x) {
    unsigned r;
    asm("cvt.rna.tf32.f32 %0, %1;" : "=r"(r) : "f"(x));
    return r;
}
__device__ __forceinline__ void cp16(unsigned s, const void* g) {
    asm volatile("cp.async.cg.shared.global [%0], [%1], 16;\n" :: "r"(s), "l"(g));
}
__device__ __forceinline__ float gelu_tanh(float x) {
    float x3 = x * x * x;
    return 0.5f * x * (1.0f + tanhf(0.7978845608028654f * (x + 0.044715f * x3)));
}

// ---------------- segment ids ----------------
__global__ void seg_kernel(const int* __restrict__ cu, int* __restrict__ seg) {
    int n = blockIdx.x * blockDim.x + threadIdx.x;
    if (n < N_TOK) {
        int s = 0;
        #pragma unroll
        for (int j = 1; j <= 8; j++) s += (cu[j] <= n) ? 1 : 0;
        seg[n] = s;
    }
}

// ---------------- tf32 tensor-core GEMM: C[M,N] = A[M,K] @ B[K,N] + bias (opt GELU) ----------------
#define BM 128
#define BN 128
#define BK 16
#define LDA 20    // BK + 4  -> fragment banks (20g+c) all distinct
#define LDB 136   // BN + 8  -> fragment banks (8c+g) all distinct

__global__ __launch_bounds__(256, 2) void tgemm_kernel(
    const float* __restrict__ A, const float* __restrict__ B,
    const float* __restrict__ bias, float* __restrict__ C,
    int M, int N, int K, int act)
{
    __shared__ float As[2][BM * LDA];   // 20480 B
    __shared__ float Bs[2][BK * LDB];   // 17408 B

    const int tid  = threadIdx.x;
    const int lane = tid & 31;
    const int warp = tid >> 5;
    const int g    = lane >> 2;         // group id 0..7
    const int c    = lane & 3;          // thread-in-group 0..3
    const int wm   = (warp >> 2) * 64;  // warp row offset
    const int wn   = (warp & 3) * 32;   // warp col offset
    const int bm   = blockIdx.y * BM;
    const int bn   = blockIdx.x * BN;

    // global->smem load mapping
    const int arow = tid >> 1;             // 0..127
    const int acol = (tid & 1) * 8;        // 0 or 8
    const int brow = tid >> 4;             // 0..15
    const int bcol = (tid & 15) * 8;       // 0..120

    const float* Ag = A + (size_t)(bm + arow) * K + acol;
    const float* Bg = B + (size_t)brow * N + bn + bcol;

    unsigned As_w[2], Bs_w[2];
    #pragma unroll
    for (int b = 0; b < 2; b++) {
        As_w[b] = (unsigned)__cvta_generic_to_shared(&As[b][arow * LDA + acol]);
        Bs_w[b] = (unsigned)__cvta_generic_to_shared(&Bs[b][brow * LDB + bcol]);
    }

    float acc[4][4][4] = {};

    const int T = K / BK;

    // prefetch tile 0 into buf 0
    {
        const float* ap = Ag;
        cp16(As_w[0], ap);      cp16(As_w[0] + 16, ap + 4);
        const float* bp = Bg;
        cp16(Bs_w[0], bp);      cp16(Bs_w[0] + 16, bp + 4);
        asm volatile("cp.async.commit_group;\n");
    }

    int buf = 0;
    for (int t = 0; t < T; t++) {
        asm volatile("cp.async.wait_group 0;\n");
        __syncthreads();
        if (t + 1 < T) {
            int nb = buf ^ 1;
            const float* ap = Ag + (t + 1) * BK;
            cp16(As_w[nb], ap);      cp16(As_w[nb] + 16, ap + 4);
            const float* bp = Bg + (size_t)(t + 1) * BK * N;
            cp16(Bs_w[nb], bp);      cp16(Bs_w[nb] + 16, bp + 4);
            asm volatile("cp.async.commit_group;\n");
        }

        const float* Ar = &As[buf][(wm + g) * LDA + c];
        const float* Br = &Bs[buf][c * LDB + wn + g];

        #pragma unroll
        for (int kk = 0; kk < 2; kk++) {
            unsigned af[4][4];
            #pragma unroll
            for (int mt = 0; mt < 4; mt++) {
                const float* p = Ar + mt * 16 * LDA + kk * 8;
                af[mt][0] = f2tf(p[0]);
                af[mt][1] = f2tf(p[8 * LDA]);
                af[mt][2] = f2tf(p[4]);
                af[mt][3] = f2tf(p[8 * LDA + 4]);
            }
            unsigned bf[4][2];
            #pragma unroll
            for (int nt = 0; nt < 4; nt++) {
                const float* p = Br + kk * 8 * LDB + nt * 8;
                bf[nt][0] = f2tf(p[0]);
                bf[nt][1] = f2tf(p[4 * LDB]);
            }
            #pragma unroll
            for (int mt = 0; mt < 4; mt++)
                #pragma unroll
                for (int nt = 0; nt < 4; nt++)
                    asm volatile(
                        "mma.sync.aligned.m16n8k8.row.col.f32.tf32.tf32.f32 "
                        "{%0,%1,%2,%3}, {%4,%5,%6,%7}, {%8,%9}, {%0,%1,%2,%3};"
                        : "+f"(acc[mt][nt][0]), "+f"(acc[mt][nt][1]),
                          "+f"(acc[mt][nt][2]), "+f"(acc[mt][nt][3])
                        : "r"(af[mt][0]), "r"(af[mt][1]), "r"(af[mt][2]), "r"(af[mt][3]),
                          "r"(bf[nt][0]), "r"(bf[nt][1]));
        }
        buf ^= 1;
    }

    // epilogue: bias (+ gelu) and store
    #pragma unroll
    for (int mt = 0; mt < 4; mt++) {
        int row0 = bm + wm + mt * 16 + g;
        #pragma unroll
        for (int nt = 0; nt < 4; nt++) {
            int col = bn + wn + nt * 8 + 2 * c;
            float b0 = bias[col], b1 = bias[col + 1];
            float2 v0 = make_float2(acc[mt][nt][0] + b0, acc[mt][nt][1] + b1);
            float2 v1 = make_float2(acc[mt][nt][2] + b0, acc[mt][nt][3] + b1);
            if (act) {
                v0.x = gelu_tanh(v0.x); v0.y = gelu_tanh(v0.y);
                v1.x = gelu_tanh(v1.x); v1.y = gelu_tanh(v1.y);
            }
            *(float2*)(C + (size_t)row0 * N + col)       = v0;
            *(float2*)(C + (size_t)(row0 + 8) * N + col) = v1;
        }
    }
}

// ---------------- RoPE (in-place on q and k slices of qkv) ----------------
__global__ __launch_bounds__(128) void rope_kernel(
    float* __restrict__ qkv, const float* __restrict__ coords,
    const float* __restrict__ inv_freq)
{
    int n = blockIdx.x;
    int t = threadIdx.x;
    __shared__ float cs[32], sn[32];
    if (t < 32) {
        float ang = coords[n * 4 + (t >> 3)] * inv_freq[t];
        cs[t] = cosf(ang);
        sn[t] = sinf(ang);
    }
    __syncthreads();
    for (int item = t; item < 1024; item += 128) {
        int i  = item & 31;
        int hs = item >> 5;
        int s  = hs & 1;
        int h  = hs >> 1;
        float* base = qkv + (size_t)n * QKV_N + s * EMBED + h * HDIM;
        float x1 = base[i], x2 = base[i + 32];
        float cc = cs[i], si = sn[i];
        base[i]      = x1 * cc - x2 * si;
        base[i + 32] = x2 * cc + x1 * si;
    }
}

// ---------------- varlen flash attention (fp32, online softmax) ----------------
__global__ __launch_bounds__(32) void attn_kernel(
    const float* __restrict__ qkv, const int* __restrict__ cu,
    const int* __restrict__ seg, float* __restrict__ out)
{
    const int lane = threadIdx.x;
    const int n = blockIdx.x * 32 + lane;
    const int h = blockIdx.y;

    float q[64];
    {
        const float4* qp = (const float4*)(qkv + (size_t)n * QKV_N + h * HDIM);
        #pragma unroll
        for (int i = 0; i < 16; i++) {
            float4 t = qp[i];
            q[4*i] = t.x; q[4*i+1] = t.y; q[4*i+2] = t.z; q[4*i+3] = t.w;
        }
    }

    const int s = seg[n];
    const int start = cu[s];
    const int end   = cu[s + 1];
    int jmin = start, jmax = end;
    #pragma unroll
    for (int off = 16; off; off >>= 1) {
        jmin = min(jmin, __shfl_xor_sync(0xffffffffu, jmin, off));
        jmax = max(jmax, __shfl_xor_sync(0xffffffffu, jmax, off));
    }

    float m = -1e30f, l = 0.f;
    float o[64];
    #pragma unroll
    for (int i = 0; i < 64; i++) o[i] = 0.f;

    for (int j = jmin; j < jmax; j++) {
        const float4* kp = (const float4*)(qkv + (size_t)j * QKV_N + EMBED + h * HDIM);
        float dot = 0.f;
        #pragma unroll
        for (int i = 0; i < 16; i++) {
            float4 t = kp[i];
            dot = fmaf(q[4*i],   t.x, dot);
            dot = fmaf(q[4*i+1], t.y, dot);
            dot = fmaf(q[4*i+2], t.z, dot);
            dot = fmaf(q[4*i+3], t.w, dot);
        }
        dot *= 0.125f;
        if (j >= start && j < end) {
            if (dot > m) {
                float sc = __expf(m - dot);
                l *= sc;
                #pragma unroll
                for (int i = 0; i < 64; i++) o[i] *= sc;
                m = dot;
            }
            float p = __expf(dot - m);
            l += p;
            const float4* vp = (const float4*)(qkv + (size_t)j * QKV_N + 2 * EMBED + h * HDIM);
            #pragma unroll
            for (int i = 0; i < 16; i++) {
                float4 t = vp[i];
                o[4*i]   = fmaf(p, t.x, o[4*i]);
                o[4*i+1] = fmaf(p, t.y, o[4*i+1]);
                o[4*i+2] = fmaf(p, t.z, o[4*i+2]);
                o[4*i+3] = fmaf(p, t.w, o[4*i+3]);
            }
        }
    }

    float inv = 1.f / l;
    float* op = out + (size_t)n * EMBED + h * HDIM;
    #pragma unroll
    for (int i = 0; i < 64; i += 4) {
        float4 t = make_float4(o[i] * inv, o[i+1] * inv, o[i+2] * inv, o[i+3] * inv);
        *(float4*)(op + i) = t;
    }
}

// ---------------- fused residual-add + LayerNorm ----------------
__global__ __launch_bounds__(256) void add_ln_kernel(
    const float* __restrict__ a, const float* __restrict__ b,
    const float* __restrict__ g, const float* __restrict__ beta,
    float* __restrict__ out)
{
    const int n = blockIdx.x;
    const int t = threadIdx.x;
    __shared__ float red[8];
    __shared__ float bc;

    float x[4];
    float s = 0.f;
    #pragma unroll
    for (int i = 0; i < 4; i++) {
        int idx = t + i * 256;
        x[i] = a[(size_t)n * EMBED + idx] + b[(size_t)n * EMBED + idx];
        s += x[i];
    }
    #pragma unroll
    for (int off = 16; off; off >>= 1) s += __shfl_xor_sync(0xffffffffu, s, off);
    if ((t & 31) == 0) red[t >> 5] = s;
    __syncthreads();
    if (t < 8) {
        float v = red[t];
        #pragma unroll
        for (int off = 4; off; off >>= 1) v += __shfl_xor_sync(0xffu, v, off);
        if (t == 0) bc = v;
    }
    __syncthreads();
    float mean = bc * (1.0f / EMBED);
    __syncthreads();

    float var = 0.f;
    #pragma unroll
    for (int i = 0; i < 4; i++) {
        float d = x[i] - mean;
        var += d * d;
    }
    #pragma unroll
    for (int off = 16; off; off >>= 1) var += __shfl_xor_sync(0xffffffffu, var, off);
    if ((t & 31) == 0) red[t >> 5] = var;
    __syncthreads();
    if (t < 8) {
        float v = red[t];
        #pragma unroll
        for (int off = 4; off; off >>= 1) v += __shfl_xor_sync(0xffu, v, off);
        if (t == 0) bc = v;
    }
    __syncthreads();
    float rstd = rsqrtf(bc * (1.0f / EMBED) + 1e-5f);

    #pragma unroll
    for (int i = 0; i < 4; i++) {
        int idx = t + i * 256;
        out[(size_t)n * EMBED + idx] = (x[i] - mean) * rstd * g[idx] + beta[idx];
    }
}

// ---------------- launch ----------------
extern "C" void kernel_launch(void* const* d_in, const int* in_sizes, int n_in,
                              void* d_out, int out_size)
{
    const float* coords  = (const float*)d_in[0];
    const float* feats   = (const float*)d_in[1];
    const int*   cu      = (const int*)  d_in[2];
    const float* Wqkv    = (const float*)d_in[3];
    const float* bqkv    = (const float*)d_in[4];
    const float* Wo      = (const float*)d_in[5];
    const float* bo      = (const float*)d_in[6];
    const float* inv_frq = (const float*)d_in[7];
    const float* ln1_g   = (const float*)d_in[8];
    const float* ln1_b   = (const float*)d_in[9];
    const float* W1      = (const float*)d_in[10];
    const float* b1      = (const float*)d_in[11];
    const float* W2      = (const float*)d_in[12];
    const float* b2      = (const float*)d_in[13];
    const float* ln2_g   = (const float*)d_in[14];
    const float* ln2_b   = (const float*)d_in[15];
    float* out = (float*)d_out;

    float *qkv, *attn, *tmp, *h, *ffn;
    int* seg;
    cudaGetSymbolAddress((void**)&qkv,  g_qkv);
    cudaGetSymbolAddress((void**)&attn, g_attn);
    cudaGetSymbolAddress((void**)&tmp,  g_tmp);
    cudaGetSymbolAddress((void**)&h,    g_h);
    cudaGetSymbolAddress((void**)&ffn,  g_ffn);
    cudaGetSymbolAddress((void**)&seg,  g_seg);

    // 1. segment ids
    seg_kernel<<<16, 256>>>(cu, seg);
    // 2. QKV projection
    tgemm_kernel<<<dim3(QKV_N / BN, N_TOK / BM), 256>>>(feats, Wqkv, bqkv, qkv,
                                                        N_TOK, QKV_N, EMBED, 0);
    // 3. RoPE on q,k
    rope_kernel<<<N_TOK, 128>>>(qkv, coords, inv_frq);
    // 4. varlen attention
    attn_kernel<<<dim3(N_TOK / 32, NHEADS), 32>>>(qkv, cu, seg, attn);
    // 5. output projection
    tgemm_kernel<<<dim3(EMBED / BN, N_TOK / BM), 256>>>(attn, Wo, bo, tmp,
                                                        N_TOK, EMBED, EMBED, 0);
    // 6. h = LN1(feats + o)
    add_ln_kernel<<<N_TOK, 256>>>(feats, tmp, ln1_g, ln1_b, h);
    // 7. FFN up + GELU
    tgemm_kernel<<<dim3(FFN / BN, N_TOK / BM), 256>>>(h, W1, b1, ffn,
                                                      N_TOK, FFN, EMBED, 1);
    // 8. FFN down
    tgemm_kernel<<<dim3(EMBED / BN, N_TOK / BM), 256>>>(ffn, W2, b2, tmp,
                                                        N_TOK, EMBED, FFN, 0);
    // 9. out = LN2(h + f)
    add_ln_kernel<<<N_TOK, 256>>>(h, tmp, ln2_g, ln2_b, out);
}

// round 8
// speedup vs baseline: 1.4403x; 1.0243x over previous
#include <cuda_runtime.h>
#include <cuda_bf16.h>
#include <cstdint>
#include <math.h>

// ---------------- problem constants ----------------
#define N_TOK   4096
#define EMBED   1024
#define NHEADS  16
#define HDIM    64
#define FFN     4096
#define QKV_N   3072

// ---------------- scratch (device globals; no allocation allowed) ----------------
__device__ float g_qkv   [N_TOK * QKV_N];
__device__ float g_attn  [N_TOK * EMBED];
__device__ float g_tmp   [N_TOK * EMBED];
__device__ float g_h     [N_TOK * EMBED];
__device__ float g_ffn   [N_TOK * FFN];
__device__ float g_rfeats[N_TOK * EMBED];
__device__ float g_rwqkv [EMBED * QKV_N];
__device__ float g_rwo   [EMBED * EMBED];
__device__ float g_rw1   [EMBED * FFN];
__device__ float g_rw2   [FFN * EMBED];
__device__ int   g_seg   [N_TOK];

// ---------------- small helpers ----------------
__device__ __forceinline__ unsigned f2tf(float x) {
    unsigned r;
    asm("cvt.rna.tf32.f32 %0, %1;" : "=r"(r) : "f"(x));
    return r;
}
__device__ __forceinline__ float rtf(float x) { return __uint_as_float(f2tf(x)); }

__device__ __forceinline__ void cp16(unsigned s, const void* g) {
    asm volatile("cp.async.cg.shared.global [%0], [%1], 16;\n" :: "r"(s), "l"(g));
}
__device__ __forceinline__ float gelu_tanh(float x) {
    float x3 = x * x * x;
    return 0.5f * x * (1.0f + tanhf(0.7978845608028654f * (x + 0.044715f * x3)));
}

// ---------------- segment ids ----------------
__global__ void seg_kernel(const int* __restrict__ cu, int* __restrict__ seg) {
    int n = blockIdx.x * blockDim.x + threadIdx.x;
    if (n < N_TOK) {
        int s = 0;
        #pragma unroll
        for (int j = 1; j <= 8; j++) s += (cu[j] <= n) ? 1 : 0;
        seg[n] = s;
    }
}

// ---------------- tf32-round copy ----------------
__global__ void round_copy(const float4* __restrict__ in, float4* __restrict__ out, int n4) {
    int i = blockIdx.x * blockDim.x + threadIdx.x;
    if (i < n4) {
        float4 v = in[i];
        v.x = rtf(v.x); v.y = rtf(v.y); v.z = rtf(v.z); v.w = rtf(v.w);
        out[i] = v;
    }
}
#define RC_GRID(n4) (((n4) + 255) / 256)

// ---------------- tf32 mma.sync GEMM: C[M,N] = A[M,K] @ B[K,N] + bias (opt GELU) ----
// A, B pre-rounded to tf32 (values exactly representable -> no cvt in inner loop).
#define BM 128
#define BN 128
#define BK 32
#define LDA 36    // BK + 4  : A fragment banks (4g + c) all distinct
#define LDB 136   // BN + 8  : B fragment banks (8c + g) all distinct
#define ASTG (BM * LDA * 4)             // 18432 B per stage
#define BSTG (BK * LDB * 4)             // 17408 B per stage
#define STG  (ASTG + BSTG)              // 35840 B
#define TG_DSMEM (2 * STG)              // 71680 B

__global__ __launch_bounds__(256) void tgemm_mma(
    const float* __restrict__ A, const float* __restrict__ B,
    const float* __restrict__ bias, float* __restrict__ C,
    int N, int K, int act)
{
    extern __shared__ float smem[];
    float* sA[2] = { smem,              smem + STG / 4 };
    float* sB[2] = { smem + ASTG / 4,   smem + (STG + ASTG) / 4 };

    const int tid  = threadIdx.x;
    const int lane = tid & 31;
    const int warp = tid >> 5;
    const int g    = lane >> 2;         // 0..7
    const int c    = lane & 3;          // 0..3
    const int wm   = (warp >> 2) * 64;  // warp row offset
    const int wn   = (warp & 3) * 32;   // warp col offset
    const int bm   = blockIdx.y * BM;
    const int bn   = blockIdx.x * BN;

    // cp.async mapping: 4 chunks of 16B each for A and B per thread per stage
    int aoff[4], boff[4];
    const float* gA[4];
    const float* gB[4];
    #pragma unroll
    for (int i = 0; i < 4; i++) {
        int ch = tid + i * 256;              // 0..1023
        int ar = ch >> 3, ac = ch & 7;       // A: 128 rows x 8 chunks
        aoff[i] = ar * LDA + ac * 4;
        gA[i] = A + (size_t)(bm + ar) * K + ac * 4;
        int br = ch >> 5, bc2 = ch & 31;     // B: 32 rows x 32 chunks
        boff[i] = br * LDB + bc2 * 4;
        gB[i] = B + (size_t)br * N + bn + bc2 * 4;
    }
    unsigned sAw[2][4], sBw[2][4];
    #pragma unroll
    for (int b = 0; b < 2; b++)
        #pragma unroll
        for (int i = 0; i < 4; i++) {
            sAw[b][i] = (unsigned)__cvta_generic_to_shared(sA[b] + aoff[i]);
            sBw[b][i] = (unsigned)__cvta_generic_to_shared(sB[b] + boff[i]);
        }

    float acc[4][4][4] = {};
    const int S = K / BK;

    // prologue: stage 0
    #pragma unroll
    for (int i = 0; i < 4; i++) { cp16(sAw[0][i], gA[i]); cp16(sBw[0][i], gB[i]); }
    asm volatile("cp.async.commit_group;\n" ::: "memory");

    for (int s = 0; s < S; s++) {
        asm volatile("cp.async.wait_group 0;\n" ::: "memory");
        __syncthreads();
        if (s + 1 < S) {
            int nb = (s + 1) & 1, ko = (s + 1) * BK;
            #pragma unroll
            for (int i = 0; i < 4; i++) {
                cp16(sAw[nb][i], gA[i] + ko);
                cp16(sBw[nb][i], gB[i] + (size_t)ko * N);
            }
            asm volatile("cp.async.commit_group;\n" ::: "memory");
        }

        const float* Ar = sA[s & 1] + (wm + g) * LDA + c;
        const float* Br = sB[s & 1] + c * LDB + wn + g;

        #pragma unroll
        for (int kk = 0; kk < 4; kk++) {
            unsigned af[4][4];
            #pragma unroll
            for (int mt = 0; mt < 4; mt++) {
                const float* p = Ar + mt * 16 * LDA + kk * 8;
                af[mt][0] = __float_as_uint(p[0]);
                af[mt][1] = __float_as_uint(p[8 * LDA]);
                af[mt][2] = __float_as_uint(p[4]);
                af[mt][3] = __float_as_uint(p[8 * LDA + 4]);
            }
            unsigned bf[4][2];
            #pragma unroll
            for (int nt = 0; nt < 4; nt++) {
                const float* p = Br + kk * 8 * LDB + nt * 8;
                bf[nt][0] = __float_as_uint(p[0]);
                bf[nt][1] = __float_as_uint(p[4 * LDB]);
            }
            #pragma unroll
            for (int mt = 0; mt < 4; mt++)
                #pragma unroll
                for (int nt = 0; nt < 4; nt++)
                    asm volatile(
                        "mma.sync.aligned.m16n8k8.row.col.f32.tf32.tf32.f32 "
                        "{%0,%1,%2,%3}, {%4,%5,%6,%7}, {%8,%9}, {%0,%1,%2,%3};"
                        : "+f"(acc[mt][nt][0]), "+f"(acc[mt][nt][1]),
                          "+f"(acc[mt][nt][2]), "+f"(acc[mt][nt][3])
                        : "r"(af[mt][0]), "r"(af[mt][1]), "r"(af[mt][2]), "r"(af[mt][3]),
                          "r"(bf[nt][0]), "r"(bf[nt][1]));
        }
    }

    // epilogue: bias (+ gelu + tf32 round of activation outputs) and store
    #pragma unroll
    for (int mt = 0; mt < 4; mt++) {
        int row0 = bm + wm + mt * 16 + g;
        #pragma unroll
        for (int nt = 0; nt < 4; nt++) {
            int col = bn + wn + nt * 8 + 2 * c;
            float b0 = bias[col], b1 = bias[col + 1];
            float2 v0 = make_float2(acc[mt][nt][0] + b0, acc[mt][nt][1] + b1);
            float2 v1 = make_float2(acc[mt][nt][2] + b0, acc[mt][nt][3] + b1);
            if (act) {
                v0.x = rtf(gelu_tanh(v0.x)); v0.y = rtf(gelu_tanh(v0.y));
                v1.x = rtf(gelu_tanh(v1.x)); v1.y = rtf(gelu_tanh(v1.y));
            }
            *(float2*)(C + (size_t)row0 * N + col)       = v0;
            *(float2*)(C + (size_t)(row0 + 8) * N + col) = v1;
        }
    }
}

// ---------------- RoPE (in-place on q and k slices of qkv) ----------------
__global__ __launch_bounds__(128) void rope_kernel(
    float* __restrict__ qkv, const float* __restrict__ coords,
    const float* __restrict__ inv_freq)
{
    int n = blockIdx.x;
    int t = threadIdx.x;
    __shared__ float cs[32], sn[32];
    if (t < 32) {
        float ang = coords[n * 4 + (t >> 3)] * inv_freq[t];
        cs[t] = cosf(ang);
        sn[t] = sinf(ang);
    }
    __syncthreads();
    for (int item = t; item < 1024; item += 128) {
        int i  = item & 31;
        int hs = item >> 5;
        int s  = hs & 1;
        int h  = hs >> 1;
        float* base = qkv + (size_t)n * QKV_N + s * EMBED + h * HDIM;
        float x1 = base[i], x2 = base[i + 32];
        float cc = cs[i], si = sn[i];
        base[i]      = x1 * cc - x2 * si;
        base[i + 32] = x2 * cc + x1 * si;
    }
}

// ---------------- varlen flash attention (fp32, online softmax) ----------------
__global__ __launch_bounds__(32) void attn_kernel(
    const float* __restrict__ qkv, const int* __restrict__ cu,
    const int* __restrict__ seg, float* __restrict__ out)
{
    const int lane = threadIdx.x;
    const int n = blockIdx.x * 32 + lane;
    const int h = blockIdx.y;

    float q[64];
    {
        const float4* qp = (const float4*)(qkv + (size_t)n * QKV_N + h * HDIM);
        #pragma unroll
        for (int i = 0; i < 16; i++) {
            float4 t = qp[i];
            q[4*i] = t.x; q[4*i+1] = t.y; q[4*i+2] = t.z; q[4*i+3] = t.w;
        }
    }

    const int s = seg[n];
    const int start = cu[s];
    const int end   = cu[s + 1];
    int jmin = start, jmax = end;
    #pragma unroll
    for (int off = 16; off; off >>= 1) {
        jmin = min(jmin, __shfl_xor_sync(0xffffffffu, jmin, off));
        jmax = max(jmax, __shfl_xor_sync(0xffffffffu, jmax, off));
    }

    float m = -1e30f, l = 0.f;
    float o[64];
    #pragma unroll
    for (int i = 0; i < 64; i++) o[i] = 0.f;

    for (int j = jmin; j < jmax; j++) {
        const float4* kp = (const float4*)(qkv + (size_t)j * QKV_N + EMBED + h * HDIM);
        float dot = 0.f;
        #pragma unroll
        for (int i = 0; i < 16; i++) {
            float4 t = kp[i];
            dot = fmaf(q[4*i],   t.x, dot);
            dot = fmaf(q[4*i+1], t.y, dot);
            dot = fmaf(q[4*i+2], t.z, dot);
            dot = fmaf(q[4*i+3], t.w, dot);
        }
        dot *= 0.125f;
        if (j >= start && j < end) {
            if (dot > m) {
                float sc = __expf(m - dot);
                l *= sc;
                #pragma unroll
                for (int i = 0; i < 64; i++) o[i] *= sc;
                m = dot;
            }
            float p = __expf(dot - m);
            l += p;
            const float4* vp = (const float4*)(qkv + (size_t)j * QKV_N + 2 * EMBED + h * HDIM);
            #pragma unroll
            for (int i = 0; i < 16; i++) {
                float4 t = vp[i];
                o[4*i]   = fmaf(p, t.x, o[4*i]);
                o[4*i+1] = fmaf(p, t.y, o[4*i+1]);
                o[4*i+2] = fmaf(p, t.z, o[4*i+2]);
                o[4*i+3] = fmaf(p, t.w, o[4*i+3]);
            }
        }
    }

    float inv = 1.f / l;
    float* op = out + (size_t)n * EMBED + h * HDIM;
    #pragma unroll
    for (int i = 0; i < 64; i += 4) {
        // tf32-round: attention output is the A operand of the O-proj GEMM
        float4 t = make_float4(rtf(o[i] * inv), rtf(o[i+1] * inv),
                               rtf(o[i+2] * inv), rtf(o[i+3] * inv));
        *(float4*)(op + i) = t;
    }
}

// ---------------- fused residual-add + LayerNorm (optional tf32 rounding) ----------------
__global__ __launch_bounds__(256) void add_ln_kernel(
    const float* __restrict__ a, const float* __restrict__ b,
    const float* __restrict__ g, const float* __restrict__ beta,
    float* __restrict__ out, int roundout)
{
    const int n = blockIdx.x;
    const int t = threadIdx.x;
    __shared__ float red[8];
    __shared__ float bc;

    float x[4];
    float s = 0.f;
    #pragma unroll
    for (int i = 0; i < 4; i++) {
        int idx = t + i * 256;
        x[i] = a[(size_t)n * EMBED + idx] + b[(size_t)n * EMBED + idx];
        s += x[i];
    }
    #pragma unroll
    for (int off = 16; off; off >>= 1) s += __shfl_xor_sync(0xffffffffu, s, off);
    if ((t & 31) == 0) red[t >> 5] = s;
    __syncthreads();
    if (t < 8) {
        float v = red[t];
        #pragma unroll
        for (int off = 4; off; off >>= 1) v += __shfl_xor_sync(0xffu, v, off);
        if (t == 0) bc = v;
    }
    __syncthreads();
    float mean = bc * (1.0f / EMBED);
    __syncthreads();

    float var = 0.f;
    #pragma unroll
    for (int i = 0; i < 4; i++) {
        float d = x[i] - mean;
        var += d * d;
    }
    #pragma unroll
    for (int off = 16; off; off >>= 1) var += __shfl_xor_sync(0xffffffffu, var, off);
    if ((t & 31) == 0) red[t >> 5] = var;
    __syncthreads();
    if (t < 8) {
        float v = red[t];
        #pragma unroll
        for (int off = 4; off; off >>= 1) v += __shfl_xor_sync(0xffu, v, off);
        if (t == 0) bc = v;
    }
    __syncthreads();
    float rstd = rsqrtf(bc * (1.0f / EMBED) + 1e-5f);

    #pragma unroll
    for (int i = 0; i < 4; i++) {
        int idx = t + i * 256;
        float v = (x[i] - mean) * rstd * g[idx] + beta[idx];
        if (roundout) v = rtf(v);
        out[(size_t)n * EMBED + idx] = v;
    }
}

// ---------------- launch ----------------
extern "C" void kernel_launch(void* const* d_in, const int* in_sizes, int n_in,
                              void* d_out, int out_size)
{
    const float* coords  = (const float*)d_in[0];
    const float* feats   = (const float*)d_in[1];
    const int*   cu      = (const int*)  d_in[2];
    const float* Wqkv    = (const float*)d_in[3];
    const float* bqkv    = (const float*)d_in[4];
    const float* Wo      = (const float*)d_in[5];
    const float* bo      = (const float*)d_in[6];
    const float* inv_frq = (const float*)d_in[7];
    const float* ln1_g   = (const float*)d_in[8];
    const float* ln1_b   = (const float*)d_in[9];
    const float* W1      = (const float*)d_in[10];
    const float* b1      = (const float*)d_in[11];
    const float* W2      = (const float*)d_in[12];
    const float* b2      = (const float*)d_in[13];
    const float* ln2_g   = (const float*)d_in[14];
    const float* ln2_b   = (const float*)d_in[15];
    float* out = (float*)d_out;

    float *qkv, *attn, *tmp, *h, *ffn, *rfeats, *rwqkv, *rwo, *rw1, *rw2;
    int* seg;
    cudaGetSymbolAddress((void**)&qkv,    g_qkv);
    cudaGetSymbolAddress((void**)&attn,   g_attn);
    cudaGetSymbolAddress((void**)&tmp,    g_tmp);
    cudaGetSymbolAddress((void**)&h,      g_h);
    cudaGetSymbolAddress((void**)&ffn,    g_ffn);
    cudaGetSymbolAddress((void**)&rfeats, g_rfeats);
    cudaGetSymbolAddress((void**)&rwqkv,  g_rwqkv);
    cudaGetSymbolAddress((void**)&rwo,    g_rwo);
    cudaGetSymbolAddress((void**)&rw1,    g_rw1);
    cudaGetSymbolAddress((void**)&rw2,    g_rw2);
    cudaGetSymbolAddress((void**)&seg,    g_seg);

    cudaFuncSetAttribute(tgemm_mma, cudaFuncAttributeMaxDynamicSharedMemorySize, TG_DSMEM);

    // element counts (float4 units) for the rounding copies
    const int n4_feats = N_TOK * EMBED / 4;
    const int n4_wqkv  = EMBED * QKV_N / 4;
    const int n4_wo    = EMBED * EMBED / 4;
    const int n4_w1    = EMBED * FFN  / 4;
    const int n4_w2    = FFN  * EMBED / 4;

    // launches 0-4 (prep) — ncu -s 5 -c 1 profiles launch #5 = QKV GEMM
    seg_kernel<<<16, 256>>>(cu, seg);                                                   // 0
    round_copy<<<RC_GRID(n4_feats), 256>>>((const float4*)feats, (float4*)rfeats, n4_feats); // 1
    round_copy<<<RC_GRID(n4_wqkv),  256>>>((const float4*)Wqkv,  (float4*)rwqkv,  n4_wqkv);  // 2
    round_copy<<<RC_GRID(n4_wo),    256>>>((const float4*)Wo,    (float4*)rwo,    n4_wo);    // 3
    round_copy<<<RC_GRID(n4_w1),    256>>>((const float4*)W1,    (float4*)rw1,    n4_w1);    // 4

    // 5: QKV projection  (profiled launch)
    tgemm_mma<<<dim3(QKV_N / BN, N_TOK / BM), 256, TG_DSMEM>>>(rfeats, rwqkv, bqkv, qkv,
                                                               QKV_N, EMBED, 0);
    // 6
    round_copy<<<RC_GRID(n4_w2), 256>>>((const float4*)W2, (float4*)rw2, n4_w2);
    // 7: RoPE
    rope_kernel<<<N_TOK, 128>>>(qkv, coords, inv_frq);
    // 8: varlen attention (rounds its output)
    attn_kernel<<<dim3(N_TOK / 32, NHEADS), 32>>>(qkv, cu, seg, attn);
    // 9: output projection
    tgemm_mma<<<dim3(EMBED / BN, N_TOK / BM), 256, TG_DSMEM>>>(attn, rwo, bo, tmp,
                                                               EMBED, EMBED, 0);
    // 10: h = LN1(feats + o)  (rounded: feeds FFN1)
    add_ln_kernel<<<N_TOK, 256>>>(feats, tmp, ln1_g, ln1_b, h, 1);
    // 11: FFN up + GELU (rounds output)
    tgemm_mma<<<dim3(FFN / BN, N_TOK / BM), 256, TG_DSMEM>>>(h, rw1, b1, ffn,
                                                             FFN, EMBED, 1);
    // 12: FFN down
    tgemm_mma<<<dim3(EMBED / BN, N_TOK / BM), 256, TG_DSMEM>>>(ffn, rw2, b2, tmp,
                                                               EMBED, FFN, 0);
    // 13: out = LN2(h + f)  (full precision)
    add_ln_kernel<<<N_TOK, 256>>>(h, tmp, ln2_g, ln2_b, out, 0);
}